// round 6
// baseline (speedup 1.0000x reference)
#include <cuda_runtime.h>

// Problem: volume [40,40,40,32] f32, M [32,32], P [32,32] -> Nk [59319,32]
//   b = (k1*39 + k2)*39 + k3
//   Nk[b,i] = sum_j x[b,j] * P[i,j] * cos(k1*a_ij) * cos(k2*a_ij) * cos(k3*a_ij)
//   a_ij = 2pi/(i*32+j+2),  x = (2x2x2 mean pool) @ M^T
#define NP   39
#define PI2F 6.2831853071795864769f

typedef unsigned long long ull;

__device__ float g_tab[39 * 1024];   // tab[k][j*32 + i] = cos(k * 2pi/(i*32+j+2))

// ---- f32x2 packed math (sm_103a) ------------------------------------------
__device__ __forceinline__ ull f2_mul(ull a, ull b) {
    ull d; asm("mul.rn.f32x2 %0, %1, %2;" : "=l"(d) : "l"(a), "l"(b)); return d;
}
__device__ __forceinline__ ull f2_fma(ull a, ull b, ull c) {
    ull d; asm("fma.rn.f32x2 %0, %1, %2, %3;" : "=l"(d) : "l"(a), "l"(b), "l"(c)); return d;
}
__device__ __forceinline__ ull f2_add(ull a, ull b) {
    ull d; asm("add.rn.f32x2 %0, %1, %2;" : "=l"(d) : "l"(a), "l"(b)); return d;
}
__device__ __forceinline__ ull f2_pack(float x) {
    ull d; asm("mov.b64 %0, {%1, %1};" : "=l"(d) : "f"(x)); return d;
}
__device__ __forceinline__ float2 f2_unpack(ull v) {
    float2 r; asm("mov.b64 {%0, %1}, %2;" : "=f"(r.x), "=f"(r.y) : "l"(v)); return r;
}

// ---------------------------------------------------------------------------
// Kernel 0: cos table via Chebyshev recurrence. grid 4 x 256.
// ---------------------------------------------------------------------------
__global__ void k_pre() {
    int t = blockIdx.x * 256 + threadIdx.x;   // t = j*32 + i
    int i = t & 31, j = t >> 5;
    float a  = PI2F / (float)(i * 32 + j + 2);
    float c1 = cosf(a);
    float twoc = 2.0f * c1;
    float cm2 = 1.0f, cm1 = c1;
    g_tab[t]        = 1.0f;
    g_tab[1024 + t] = c1;
#pragma unroll
    for (int k = 2; k < 39; k++) {
        float ck = twoc * cm1 - cm2;
        g_tab[k * 1024 + t] = ck;
        cm2 = cm1; cm1 = ck;
    }
}

// ---------------------------------------------------------------------------
// Fused kernel: pooling (direct from global) + x-matvec + main contraction.
// grid (10, 39): blockIdx.x = k2 tile of 4 (c), blockIdx.y = k1. 320 threads.
// Smem cut to 70.2KB and regs capped -> 3 blocks/SM, single wave (390 <= 444).
// ---------------------------------------------------------------------------
// Shared memory float offsets (17968 floats = 70.2 KB):
#define S_A     0        // 4096   A[c][j*32+i]
#define S_X     4096     // 5120   x[c][j*40 + k3]
#define S_PS    9216     // 1056   P padded [i*33 + j]
#define S_MS    10272    // 1056   M padded [j*33 + l]
#define S_MT    11328    // 1024   MT[l*32 + j]
#define S_POOL  12352    // 5616   pooled[c][k3*36 + ch]   (dead after phase C)
#define S_PART  12352    // 5440   partials (overlaps POOL)
#define SMEM_FLOATS 17968

__global__ void __launch_bounds__(320, 3) k_fused(
    const float* __restrict__ vol, const float* __restrict__ M,
    const float* __restrict__ P, float* __restrict__ out)
{
    extern __shared__ float sm[];
    const int k1  = blockIdx.y;
    const int k2b = blockIdx.x * 4;
    const int tid = threadIdx.x;

    // -------- Phase A: stage P, M (padded) --------
    for (int g = tid; g < 1024; g += 320) {
        sm[S_PS + (g >> 5) * 33 + (g & 31)] = P[g];
        sm[S_MS + (g >> 5) * 33 + (g & 31)] = M[g];
    }
    __syncthreads();

    // -------- Phase B: pooling directly from global + MT transpose --------
    for (int p4 = tid; p4 < 1248; p4 += 320) {
        int c   = p4 / 312;
        int rem = p4 - c * 312;
        int k3  = rem >> 3;
        int cq  = rem & 7;
        int k2c = k2b + c; if (k2c > 38) k2c = 38;    // clamp (x zeroed later)
        const float* base = vol + (((k1 * 40) + k2c) * 40 + k3) * 32 + cq * 4;
        float4 s = make_float4(0.f, 0.f, 0.f, 0.f);
#pragma unroll
        for (int dd = 0; dd < 2; dd++)
#pragma unroll
            for (int hh = 0; hh < 2; hh++)
#pragma unroll
                for (int ww = 0; ww < 2; ww++) {
                    float4 v = *(const float4*)(base + dd * 51200 + hh * 1280 + ww * 32);
                    s.x += v.x; s.y += v.y; s.z += v.z; s.w += v.w;
                }
        s.x *= 0.125f; s.y *= 0.125f; s.z *= 0.125f; s.w *= 0.125f;
        *(float4*)&sm[S_POOL + c * 1404 + k3 * 36 + cq * 4] = s;
    }
    for (int t = tid; t < 1024; t += 320)
        sm[S_MT + t] = sm[S_MS + (t & 31) * 33 + (t >> 5)];
    __syncthreads();

    // -------- Phase C: A staging + x matvec --------
    for (int idx = tid; idx < 4096; idx += 320) {
        int c = idx >> 10;
        int t = idx & 1023;
        float a = 0.f;
        if (k2b + c < NP)
            a = sm[S_PS + (t & 31) * 33 + (t >> 5)]
              * g_tab[k1 * 1024 + t] * g_tab[(k2b + c) * 1024 + t];
        sm[S_A + idx] = a;
    }
    // x[c][j][k3] ; jobs cover k3=0..39 (k3=39 and invalid c write zeros)
    for (int job = tid; job < 1280; job += 320) {
        int c   = job / 320;
        int rem = job - c * 320;
        int k3  = rem >> 3;
        int jq  = rem & 7;
        float a0 = 0.f, a1 = 0.f, a2 = 0.f, a3 = 0.f;
        if (k3 < NP && (k2b + c) < NP) {
#pragma unroll
            for (int l = 0; l < 32; l++) {
                float p = sm[S_POOL + c * 1404 + k3 * 36 + l];
                float4 m4 = *(const float4*)&sm[S_MT + l * 32 + jq * 4];
                a0 += p * m4.x; a1 += p * m4.y; a2 += p * m4.z; a3 += p * m4.w;
            }
        }
        sm[S_X + c * 1280 + (jq * 4 + 0) * 40 + k3] = a0;
        sm[S_X + c * 1280 + (jq * 4 + 1) * 40 + k3] = a1;
        sm[S_X + c * 1280 + (jq * 4 + 2) * 40 + k3] = a2;
        sm[S_X + c * 1280 + (jq * 4 + 3) * 40 + k3] = a3;
    }
    __syncthreads();

    // -------- Phase D: main contraction, j split across two groups --------
    const int jg  = tid >= 160;
    const int s   = tid - jg * 160;
    const int iq  = s & 7;
    const int k3p = s >> 3;              // 0..19 ; k3 = k3p*2 + t

    const ulonglong2* c3p[2];
#pragma unroll
    for (int t = 0; t < 2; t++) {
        int k3 = k3p * 2 + t; if (k3 > 38) k3 = 38;   // k3=39: x zeroed
        c3p[t] = (const ulonglong2*)(g_tab + k3 * 1024 + iq * 4);
    }
    const ulonglong2* ap = (const ulonglong2*)(sm + S_A + iq * 4);
    const float2*     xp = (const float2*)(sm + S_X);

    ull acc[4][2][2];
#pragma unroll
    for (int c = 0; c < 4; c++)
#pragma unroll
        for (int t = 0; t < 2; t++) { acc[c][t][0] = 0ull; acc[c][t][1] = 0ull; }

    const int j0 = jg * 16;
#pragma unroll 2
    for (int jj = 0; jj < 16; jj++) {
        int j = j0 + jj;
        ulonglong2 c3[2];
#pragma unroll
        for (int t = 0; t < 2; t++) c3[t] = c3p[t][j * 8];

        ulonglong2 a[4];
        float2     xv[4];
#pragma unroll
        for (int c = 0; c < 4; c++) {
            a[c]  = ap[c * 256 + j * 8];
            xv[c] = xp[(c * 1280 + j * 40) / 2 + k3p];
        }
#pragma unroll
        for (int c = 0; c < 4; c++) {
            ull xd0 = f2_pack(xv[c].x);
            ull xd1 = f2_pack(xv[c].y);
            acc[c][0][0] = f2_fma(f2_mul(a[c].x, xd0), c3[0].x, acc[c][0][0]);
            acc[c][0][1] = f2_fma(f2_mul(a[c].y, xd0), c3[0].y, acc[c][0][1]);
            acc[c][1][0] = f2_fma(f2_mul(a[c].x, xd1), c3[1].x, acc[c][1][0]);
            acc[c][1][1] = f2_fma(f2_mul(a[c].y, xd1), c3[1].y, acc[c][1][1]);
        }
    }

    // -------- Phase E: cross-group reduction + store --------
    ull* part = (ull*)(sm + S_PART);
    if (jg == 1) {
#pragma unroll
        for (int c = 0; c < 4; c++)
#pragma unroll
            for (int t = 0; t < 2; t++) {
                part[s * 17 + c * 4 + t * 2 + 0] = acc[c][t][0];
                part[s * 17 + c * 4 + t * 2 + 1] = acc[c][t][1];
            }
    }
    __syncthreads();
    if (jg == 0) {
#pragma unroll
        for (int c = 0; c < 4; c++) {
            if (k2b + c >= NP) continue;
#pragma unroll
            for (int t = 0; t < 2; t++) {
                int k3 = k3p * 2 + t;
                if (k3 >= NP) continue;
                ull lo = f2_add(acc[c][t][0], part[s * 17 + c * 4 + t * 2 + 0]);
                ull hi = f2_add(acc[c][t][1], part[s * 17 + c * 4 + t * 2 + 1]);
                float2 l2 = f2_unpack(lo);
                float2 h2 = f2_unpack(hi);
                int b = ((k1 * NP) + k2b + c) * NP + k3;
                *(float4*)&out[b * 32 + iq * 4] = make_float4(l2.x, l2.y, h2.x, h2.y);
            }
        }
    }
}

// ---------------------------------------------------------------------------
extern "C" void kernel_launch(void* const* d_in, const int* in_sizes, int n_in,
                              void* d_out, int out_size) {
    const float* vol = (const float*)d_in[0];
    const float* M   = (const float*)d_in[1];
    const float* P   = (const float*)d_in[2];
    float* out = (float*)d_out;

    static int attr_set = 0;
    if (!attr_set) {
        cudaFuncSetAttribute(k_fused, cudaFuncAttributeMaxDynamicSharedMemorySize,
                             SMEM_FLOATS * 4);
        attr_set = 1;
    }
    k_pre  <<<4, 256>>>();
    k_fused<<<dim3(10, 39), 320, SMEM_FLOATS * 4>>>(vol, M, P, out);
}

// round 7
// speedup vs baseline: 1.6256x; 1.6256x over previous
#include <cuda_runtime.h>

// Problem: volume [40,40,40,32] f32, M [32,32], P [32,32] -> Nk [59319,32]
//   b = (k1*39 + k2)*39 + k3
//   Nk[b,i] = sum_j x[b,j] * P[i,j] * cos(k1*a_ij) * cos(k2*a_ij) * cos(k3*a_ij)
//   a_ij = 2pi/(i*32+j+2),  x = (2x2x2 mean pool) @ M^T
#define NP   39
#define PI2F 6.2831853071795864769f

typedef unsigned long long ull;

__device__ float g_tab[39 * 1024];   // tab[k][j*32 + i] = cos(k * 2pi/(i*32+j+2))

// ---- f32x2 packed math (sm_103a) ------------------------------------------
__device__ __forceinline__ ull f2_mul(ull a, ull b) {
    ull d; asm("mul.rn.f32x2 %0, %1, %2;" : "=l"(d) : "l"(a), "l"(b)); return d;
}
__device__ __forceinline__ ull f2_fma(ull a, ull b, ull c) {
    ull d; asm("fma.rn.f32x2 %0, %1, %2, %3;" : "=l"(d) : "l"(a), "l"(b), "l"(c)); return d;
}
__device__ __forceinline__ ull f2_pack(float x) {
    ull d; asm("mov.b64 %0, {%1, %1};" : "=l"(d) : "f"(x)); return d;
}
__device__ __forceinline__ float2 f2_unpack(ull v) {
    float2 r; asm("mov.b64 {%0, %1}, %2;" : "=f"(r.x), "=f"(r.y) : "l"(v)); return r;
}

// ---------------------------------------------------------------------------
// Kernel 0: cos table via Chebyshev recurrence. grid 4 x 256.
// ---------------------------------------------------------------------------
__global__ void k_pre() {
    int t = blockIdx.x * 256 + threadIdx.x;   // t = j*32 + i
    int i = t & 31, j = t >> 5;
    float a  = PI2F / (float)(i * 32 + j + 2);
    float c1 = cosf(a);
    float twoc = 2.0f * c1;
    float cm2 = 1.0f, cm1 = c1;
    g_tab[t]        = 1.0f;
    g_tab[1024 + t] = c1;
#pragma unroll
    for (int k = 2; k < 39; k++) {
        float ck = twoc * cm1 - cm2;
        g_tab[k * 1024 + t] = ck;
        cm2 = cm1; cm1 = ck;
    }
}

// ---------------------------------------------------------------------------
// Fused kernel: pooling + x-matvec + main contraction.
// grid (10, 39): blockIdx.x = k2 tile of 4 (c), blockIdx.y = k1. 320 threads.
// Phase D: thread = (k3 = tid>>3 in 0..39, iq = tid&7); 4c x 4i outputs,
// 8 ull accumulators -> ~55 natural regs, 3 blocks/SM without spills.
// Smem 54.2 KB (A overlaps POOL after the x-matvec finishes).
// ---------------------------------------------------------------------------
// Shared memory float offsets (13872 floats = 54.2 KB):
#define S_PS    0        // 1056   P padded [i*33 + j]
#define S_MS    1056     // 1056   M padded [j*33 + l]
#define S_MT    2112     // 1024   MT[l*32 + j]
#define S_X     3136     // 5120   x[c][j*40 + k3]
#define S_POOL  8256     // 5616   pooled[c][k3*36 + ch]  (dead after phase C1)
#define S_A     8256     // 4096   A[c][j*32+i]           (overlaps POOL)
#define SMEM_FLOATS 13872

__global__ void __launch_bounds__(320, 3) k_fused(
    const float* __restrict__ vol, const float* __restrict__ M,
    const float* __restrict__ P, float* __restrict__ out)
{
    extern __shared__ float sm[];
    const int k1  = blockIdx.y;
    const int k2b = blockIdx.x * 4;
    const int tid = threadIdx.x;

    // -------- Phase A: stage P, M (padded) --------
    for (int g = tid; g < 1024; g += 320) {
        sm[S_PS + (g >> 5) * 33 + (g & 31)] = P[g];
        sm[S_MS + (g >> 5) * 33 + (g & 31)] = M[g];
    }
    __syncthreads();

    // -------- Phase B: pooling directly from global + MT transpose --------
    for (int p4 = tid; p4 < 1248; p4 += 320) {
        int c   = p4 / 312;
        int rem = p4 - c * 312;
        int k3  = rem >> 3;
        int cq  = rem & 7;
        int k2c = k2b + c; if (k2c > 38) k2c = 38;    // clamp (x zeroed later)
        const float* base = vol + (((k1 * 40) + k2c) * 40 + k3) * 32 + cq * 4;
        float4 s = make_float4(0.f, 0.f, 0.f, 0.f);
#pragma unroll
        for (int dd = 0; dd < 2; dd++)
#pragma unroll
            for (int hh = 0; hh < 2; hh++)
#pragma unroll
                for (int ww = 0; ww < 2; ww++) {
                    float4 v = *(const float4*)(base + dd * 51200 + hh * 1280 + ww * 32);
                    s.x += v.x; s.y += v.y; s.z += v.z; s.w += v.w;
                }
        s.x *= 0.125f; s.y *= 0.125f; s.z *= 0.125f; s.w *= 0.125f;
        *(float4*)&sm[S_POOL + c * 1404 + k3 * 36 + cq * 4] = s;
    }
    for (int t = tid; t < 1024; t += 320)
        sm[S_MT + t] = sm[S_MS + (t & 31) * 33 + (t >> 5)];
    __syncthreads();

    // -------- Phase C1: x matvec (reads POOL) --------
    // x[c][j][k3] ; jobs cover k3=0..39 (k3=39 and invalid c write zeros)
    for (int job = tid; job < 1280; job += 320) {
        int c   = job / 320;
        int rem = job - c * 320;
        int k3  = rem >> 3;
        int jq  = rem & 7;
        float a0 = 0.f, a1 = 0.f, a2 = 0.f, a3 = 0.f;
        if (k3 < NP && (k2b + c) < NP) {
#pragma unroll
            for (int l = 0; l < 32; l++) {
                float p = sm[S_POOL + c * 1404 + k3 * 36 + l];
                float4 m4 = *(const float4*)&sm[S_MT + l * 32 + jq * 4];
                a0 += p * m4.x; a1 += p * m4.y; a2 += p * m4.z; a3 += p * m4.w;
            }
        }
        sm[S_X + c * 1280 + (jq * 4 + 0) * 40 + k3] = a0;
        sm[S_X + c * 1280 + (jq * 4 + 1) * 40 + k3] = a1;
        sm[S_X + c * 1280 + (jq * 4 + 2) * 40 + k3] = a2;
        sm[S_X + c * 1280 + (jq * 4 + 3) * 40 + k3] = a3;
    }
    __syncthreads();

    // -------- Phase C2: A staging (overwrites POOL) --------
    for (int idx = tid; idx < 4096; idx += 320) {
        int c = idx >> 10;
        int t = idx & 1023;
        float a = 0.f;
        if (k2b + c < NP)
            a = sm[S_PS + (t & 31) * 33 + (t >> 5)]
              * g_tab[k1 * 1024 + t] * g_tab[(k2b + c) * 1024 + t];
        sm[S_A + idx] = a;
    }
    __syncthreads();

    // -------- Phase D: main contraction --------
    const int iq = tid & 7;
    const int k3 = tid >> 3;             // 0..39 (k3=39: compute, skip store)
    const int k3c = (k3 > 38) ? 38 : k3;

    const ulonglong2* c3p = (const ulonglong2*)(g_tab + k3c * 1024 + iq * 4);
    const ulonglong2* ap  = (const ulonglong2*)(sm + S_A + iq * 4);
    const float*      xp  = sm + S_X + k3;

    ull acc[4][2];
#pragma unroll
    for (int c = 0; c < 4; c++) { acc[c][0] = 0ull; acc[c][1] = 0ull; }

#pragma unroll 2
    for (int j = 0; j < 32; j++) {
        ulonglong2 c3 = __ldg(c3p + j * 8);
#pragma unroll
        for (int c = 0; c < 4; c++) {
            float xv = xp[c * 1280 + j * 40];
            ulonglong2 a = ap[c * 256 + j * 8];
            ull xd = f2_pack(xv);
            acc[c][0] = f2_fma(f2_mul(a.x, xd), c3.x, acc[c][0]);
            acc[c][1] = f2_fma(f2_mul(a.y, xd), c3.y, acc[c][1]);
        }
    }

    // -------- Store --------
    if (k3 < NP) {
#pragma unroll
        for (int c = 0; c < 4; c++) {
            if (k2b + c >= NP) continue;
            float2 lo = f2_unpack(acc[c][0]);
            float2 hi = f2_unpack(acc[c][1]);
            int b = ((k1 * NP) + k2b + c) * NP + k3;
            *(float4*)&out[b * 32 + iq * 4] = make_float4(lo.x, lo.y, hi.x, hi.y);
        }
    }
}

// ---------------------------------------------------------------------------
extern "C" void kernel_launch(void* const* d_in, const int* in_sizes, int n_in,
                              void* d_out, int out_size) {
    const float* vol = (const float*)d_in[0];
    const float* M   = (const float*)d_in[1];
    const float* P   = (const float*)d_in[2];
    float* out = (float*)d_out;

    static int attr_set = 0;
    if (!attr_set) {
        cudaFuncSetAttribute(k_fused, cudaFuncAttributeMaxDynamicSharedMemorySize,
                             SMEM_FLOATS * 4);
        attr_set = 1;
    }
    k_pre  <<<4, 256>>>();
    k_fused<<<dim3(10, 39), 320, SMEM_FLOATS * 4>>>(vol, M, P, out);
}

// round 8
// speedup vs baseline: 1.6359x; 1.0063x over previous
#include <cuda_runtime.h>

// Problem: volume [40,40,40,32] f32, M [32,32], P [32,32] -> Nk [59319,32]
//   b = (k1*39 + k2)*39 + k3
//   Nk[b,i] = sum_j x[b,j] * P[i,j] * cos(k1*a_ij) * cos(k2*a_ij) * cos(k3*a_ij)
//   a_ij = 2pi/(i*32+j+2),  x = (2x2x2 mean pool) @ M^T
#define NP   39
#define PI2F 6.2831853071795864769f

typedef unsigned long long ull;

__device__ float g_tab[39 * 1024];   // tab[k][j*32 + i] = cos(k * 2pi/(i*32+j+2))

// ---- f32x2 packed math (sm_103a) ------------------------------------------
__device__ __forceinline__ ull f2_mul(ull a, ull b) {
    ull d; asm("mul.rn.f32x2 %0, %1, %2;" : "=l"(d) : "l"(a), "l"(b)); return d;
}
__device__ __forceinline__ ull f2_fma(ull a, ull b, ull c) {
    ull d; asm("fma.rn.f32x2 %0, %1, %2, %3;" : "=l"(d) : "l"(a), "l"(b), "l"(c)); return d;
}
__device__ __forceinline__ ull f2_pack(float x) {
    ull d; asm("mov.b64 %0, {%1, %1};" : "=l"(d) : "f"(x)); return d;
}
__device__ __forceinline__ float2 f2_unpack(ull v) {
    float2 r; asm("mov.b64 {%0, %1}, %2;" : "=f"(r.x), "=f"(r.y) : "l"(v)); return r;
}

// ---------------------------------------------------------------------------
// Kernel 0: cos table via Chebyshev recurrence. grid 4 x 256.
// ---------------------------------------------------------------------------
__global__ void k_pre() {
    int t = blockIdx.x * 256 + threadIdx.x;   // t = j*32 + i
    int i = t & 31, j = t >> 5;
    float a  = PI2F / (float)(i * 32 + j + 2);
    float c1 = cosf(a);
    float twoc = 2.0f * c1;
    float cm2 = 1.0f, cm1 = c1;
    g_tab[t]        = 1.0f;
    g_tab[1024 + t] = c1;
#pragma unroll
    for (int k = 2; k < 39; k++) {
        float ck = twoc * cm1 - cm2;
        g_tab[k * 1024 + t] = ck;
        cm2 = cm1; cm1 = ck;
    }
}

// ---------------------------------------------------------------------------
// Fused kernel: pooling + x-matvec + main contraction.
// grid (10, 39): blockIdx.x = k2 tile of 4 (c), blockIdx.y = k1. 320 threads.
// Phase D: thread = (k3 = tid>>3 in 0..39, iq = tid&7); 4c x 4i outputs,
// 8 ull accumulators -> ~55 natural regs, 3 blocks/SM without spills.
// Smem 54.2 KB (A overlaps POOL after the x-matvec finishes).
// ---------------------------------------------------------------------------
// Shared memory float offsets (13872 floats = 54.2 KB):
#define S_PS    0        // 1056   P padded [i*33 + j]
#define S_MS    1056     // 1056   M padded [j*33 + l]
#define S_MT    2112     // 1024   MT[l*32 + j]
#define S_X     3136     // 5120   x[c][j*40 + k3]
#define S_POOL  8256     // 5616   pooled[c][k3*36 + ch]  (dead after phase C1)
#define S_A     8256     // 4096   A[c][j*32+i]           (overlaps POOL)
#define SMEM_FLOATS 13872

__global__ void __launch_bounds__(320, 3) k_fused(
    const float* __restrict__ vol, const float* __restrict__ M,
    const float* __restrict__ P, float* __restrict__ out)
{
    extern __shared__ float sm[];
    const int k1  = blockIdx.y;
    const int k2b = blockIdx.x * 4;
    const int tid = threadIdx.x;

    // -------- Phase A: stage P, M (padded) --------
    for (int g = tid; g < 1024; g += 320) {
        sm[S_PS + (g >> 5) * 33 + (g & 31)] = P[g];
        sm[S_MS + (g >> 5) * 33 + (g & 31)] = M[g];
    }
    __syncthreads();

    // -------- Phase B: pooling directly from global + MT transpose --------
    for (int p4 = tid; p4 < 1248; p4 += 320) {
        int c   = p4 / 312;
        int rem = p4 - c * 312;
        int k3  = rem >> 3;
        int cq  = rem & 7;
        int k2c = k2b + c; if (k2c > 38) k2c = 38;    // clamp (x zeroed later)
        const float* base = vol + (((k1 * 40) + k2c) * 40 + k3) * 32 + cq * 4;
        float4 s = make_float4(0.f, 0.f, 0.f, 0.f);
#pragma unroll
        for (int dd = 0; dd < 2; dd++)
#pragma unroll
            for (int hh = 0; hh < 2; hh++)
#pragma unroll
                for (int ww = 0; ww < 2; ww++) {
                    float4 v = *(const float4*)(base + dd * 51200 + hh * 1280 + ww * 32);
                    s.x += v.x; s.y += v.y; s.z += v.z; s.w += v.w;
                }
        s.x *= 0.125f; s.y *= 0.125f; s.z *= 0.125f; s.w *= 0.125f;
        *(float4*)&sm[S_POOL + c * 1404 + k3 * 36 + cq * 4] = s;
    }
    for (int t = tid; t < 1024; t += 320)
        sm[S_MT + t] = sm[S_MS + (t & 31) * 33 + (t >> 5)];
    __syncthreads();

    // -------- Phase C1: x matvec (reads POOL) --------
    // x[c][j][k3] ; jobs cover k3=0..39 (k3=39 and invalid c write zeros)
    for (int job = tid; job < 1280; job += 320) {
        int c   = job / 320;
        int rem = job - c * 320;
        int k3  = rem >> 3;
        int jq  = rem & 7;
        float a0 = 0.f, a1 = 0.f, a2 = 0.f, a3 = 0.f;
        if (k3 < NP && (k2b + c) < NP) {
#pragma unroll
            for (int l = 0; l < 32; l++) {
                float p = sm[S_POOL + c * 1404 + k3 * 36 + l];
                float4 m4 = *(const float4*)&sm[S_MT + l * 32 + jq * 4];
                a0 += p * m4.x; a1 += p * m4.y; a2 += p * m4.z; a3 += p * m4.w;
            }
        }
        sm[S_X + c * 1280 + (jq * 4 + 0) * 40 + k3] = a0;
        sm[S_X + c * 1280 + (jq * 4 + 1) * 40 + k3] = a1;
        sm[S_X + c * 1280 + (jq * 4 + 2) * 40 + k3] = a2;
        sm[S_X + c * 1280 + (jq * 4 + 3) * 40 + k3] = a3;
    }
    __syncthreads();

    // -------- Phase C2: A staging (overwrites POOL) --------
    for (int idx = tid; idx < 4096; idx += 320) {
        int c = idx >> 10;
        int t = idx & 1023;
        float a = 0.f;
        if (k2b + c < NP)
            a = sm[S_PS + (t & 31) * 33 + (t >> 5)]
              * g_tab[k1 * 1024 + t] * g_tab[(k2b + c) * 1024 + t];
        sm[S_A + idx] = a;
    }
    __syncthreads();

    // -------- Phase D: main contraction --------
    const int iq = tid & 7;
    const int k3 = tid >> 3;             // 0..39 (k3=39: compute, skip store)
    const int k3c = (k3 > 38) ? 38 : k3;

    const ulonglong2* c3p = (const ulonglong2*)(g_tab + k3c * 1024 + iq * 4);
    const ulonglong2* ap  = (const ulonglong2*)(sm + S_A + iq * 4);
    const float*      xp  = sm + S_X + k3;

    ull acc[4][2];
#pragma unroll
    for (int c = 0; c < 4; c++) { acc[c][0] = 0ull; acc[c][1] = 0ull; }

#pragma unroll 2
    for (int j = 0; j < 32; j++) {
        ulonglong2 c3 = __ldg(c3p + j * 8);
#pragma unroll
        for (int c = 0; c < 4; c++) {
            float xv = xp[c * 1280 + j * 40];
            ulonglong2 a = ap[c * 256 + j * 8];
            ull xd = f2_pack(xv);
            acc[c][0] = f2_fma(f2_mul(a.x, xd), c3.x, acc[c][0]);
            acc[c][1] = f2_fma(f2_mul(a.y, xd), c3.y, acc[c][1]);
        }
    }

    // -------- Store --------
    if (k3 < NP) {
#pragma unroll
        for (int c = 0; c < 4; c++) {
            if (k2b + c >= NP) continue;
            float2 lo = f2_unpack(acc[c][0]);
            float2 hi = f2_unpack(acc[c][1]);
            int b = ((k1 * NP) + k2b + c) * NP + k3;
            *(float4*)&out[b * 32 + iq * 4] = make_float4(lo.x, lo.y, hi.x, hi.y);
        }
    }
}

// ---------------------------------------------------------------------------
extern "C" void kernel_launch(void* const* d_in, const int* in_sizes, int n_in,
                              void* d_out, int out_size) {
    const float* vol = (const float*)d_in[0];
    const float* M   = (const float*)d_in[1];
    const float* P   = (const float*)d_in[2];
    float* out = (float*)d_out;

    static int attr_set = 0;
    if (!attr_set) {
        cudaFuncSetAttribute(k_fused, cudaFuncAttributeMaxDynamicSharedMemorySize,
                             SMEM_FLOATS * 4);
        attr_set = 1;
    }
    k_pre  <<<4, 256>>>();
    k_fused<<<dim3(10, 39), 320, SMEM_FLOATS * 4>>>(vol, M, P, out);
}

// round 9
// speedup vs baseline: 2.1074x; 1.2882x over previous
#include <cuda_runtime.h>

// Problem: volume [40,40,40,32] f32, M [32,32], P [32,32] -> Nk [59319,32]
//   b = (k1*39 + k2)*39 + k3
//   Nk[b,i] = sum_j x[b,j] * P[i,j] * cos(k1*a_ij) * cos(k2*a_ij) * cos(k3*a_ij)
//   a_ij = 2pi/(i*32+j+2),  x = (2x2x2 mean pool) @ M^T
//
// k_fused: one warp per (k1,k2) pair. Lane = i. j packed into 16 f32x2 regs.
// k3 marched by in-register Chebyshev recurrence (NO cos loads in hot loop):
//   u_k = 2c*u_{k-1} - u_{k-2};  w_k = s_k*u_k, s = (+,+,-,-) period 4
//   even k: w = fma(-2c, w1, w0); odd k: w = fma(+2c, w0, w1)  (pure FMA)
// Sign s_k folded into staged x rows; s^2 = 1 cancels in the product.
#define NP    39
#define NPAIR (39*39)     // 1521
#define WPB   12          // pairs (warps) per block
#define TPB   (WPB*32)    // 384
#define PI2F  6.2831853071795864769f

typedef unsigned long long ull;

__device__ float g_tab[39 * 1024];   // tab[k][j*32+i] = cos(k*2pi/(i*32+j+2))

// ---- f32x2 packed math (sm_103a) ------------------------------------------
__device__ __forceinline__ ull f2_fma(ull a, ull b, ull c) {
    ull d; asm("fma.rn.f32x2 %0, %1, %2, %3;" : "=l"(d) : "l"(a), "l"(b), "l"(c)); return d;
}
__device__ __forceinline__ ull f2_add(ull a, ull b) {
    ull d; asm("add.rn.f32x2 %0, %1, %2;" : "=l"(d) : "l"(a), "l"(b)); return d;
}
__device__ __forceinline__ ull f2_pack2(float lo, float hi) {
    ull d; asm("mov.b64 %0, {%1, %2};" : "=l"(d) : "f"(lo), "f"(hi)); return d;
}
__device__ __forceinline__ float2 f2_unpack(ull v) {
    float2 r; asm("mov.b64 {%0, %1}, %2;" : "=f"(r.x), "=f"(r.y) : "l"(v)); return r;
}

// ---------------------------------------------------------------------------
// Kernel 0: cos table via Chebyshev recurrence. grid 4 x 256.
// ---------------------------------------------------------------------------
__global__ void k_pre() {
    int t = blockIdx.x * 256 + threadIdx.x;   // t = j*32 + i
    int i = t & 31, j = t >> 5;
    float a  = PI2F / (float)(i * 32 + j + 2);
    float c1 = cosf(a);
    float twoc = 2.0f * c1;
    float cm2 = 1.0f, cm1 = c1;
    g_tab[t]        = 1.0f;
    g_tab[1024 + t] = c1;
#pragma unroll
    for (int k = 2; k < 39; k++) {
        float ck = twoc * cm1 - cm2;
        g_tab[k * 1024 + t] = ck;
        cm2 = cm1; cm1 = ck;
    }
}

// ---------------------------------------------------------------------------
// Fused kernel. grid 127 x 384 threads; 139.8 KB dynamic smem.
// ---------------------------------------------------------------------------
// smem float offsets:
#define S_MS    0        // 1056   M padded  [j*33 + l]
#define S_PT    1056     // 1056   P^T padded [j*33 + i]
#define S_MT    2112     // 1024   MT[l*32 + j] = M[j][l]
#define S_POOL  3136     // 12*1404 = 16848  pooled[lp][k3*36 + ch]
#define S_X     19984    // 12*1248 = 14976  x'[lp][k3*32 + j] (sign folded)
#define SMEM_FLOATS 34960

__global__ void __launch_bounds__(TPB) k_fused(
    const float* __restrict__ vol, const float* __restrict__ Mw,
    const float* __restrict__ P, float* __restrict__ out)
{
    extern __shared__ float sm[];
    const int tid  = threadIdx.x;
    const int wid  = tid >> 5;
    const int lane = tid & 31;
    const int pair = blockIdx.x * WPB + wid;
    const bool valid = (pair < NPAIR);

    // -------- Phase A: stage padded M and transposed-padded P --------
    for (int g = tid; g < 1024; g += TPB) {
        sm[S_MS + (g >> 5) * 33 + (g & 31)] = Mw[g];          // MS[j][l]
        sm[S_PT + (g & 31) * 33 + (g >> 5)] = P[g];           // PT[j][i] = P[i][j]
    }
    __syncthreads();

    // -------- Phase B: MT transpose + pooling (12 pairs) --------
    for (int t = tid; t < 1024; t += TPB)
        sm[S_MT + t] = sm[S_MS + (t & 31) * 33 + (t >> 5)];   // MT[l][j] = M[j][l]

    for (int job = tid; job < WPB * 312; job += TPB) {
        int lp  = job / 312;
        int rem = job - lp * 312;
        int k3  = rem >> 3;
        int cq  = rem & 7;
        int gp  = blockIdx.x * WPB + lp;
        if (gp >= NPAIR) continue;
        int kk1 = gp / 39, kk2 = gp - kk1 * 39;
        const float* base = vol + (((kk1 * 40) + kk2) * 40 + k3) * 32 + cq * 4;
        float4 s = make_float4(0.f, 0.f, 0.f, 0.f);
#pragma unroll
        for (int dd = 0; dd < 2; dd++)
#pragma unroll
            for (int hh = 0; hh < 2; hh++)
#pragma unroll
                for (int ww = 0; ww < 2; ww++) {
                    float4 v = *(const float4*)(base + dd * 51200 + hh * 1280 + ww * 32);
                    s.x += v.x; s.y += v.y; s.z += v.z; s.w += v.w;
                }
        s.x *= 0.125f; s.y *= 0.125f; s.z *= 0.125f; s.w *= 0.125f;
        *(float4*)&sm[S_POOL + lp * 1404 + k3 * 36 + cq * 4] = s;
    }
    __syncthreads();

    // -------- Phase C: matvec x'[lp][k3][j] = s_k3 * (pooled @ M^T) --------
    for (int job = tid; job < WPB * 312; job += TPB) {
        int lp  = job / 312;
        int rem = job - lp * 312;
        int k3  = rem >> 3;
        int jq  = rem & 7;
        int gp  = blockIdx.x * WPB + lp;
        if (gp >= NPAIR) continue;
        float a0 = 0.f, a1 = 0.f, a2 = 0.f, a3 = 0.f;
#pragma unroll
        for (int l = 0; l < 32; l++) {
            float p4 = sm[S_POOL + lp * 1404 + k3 * 36 + l];
            float4 m4 = *(const float4*)&sm[S_MT + l * 32 + jq * 4];
            a0 += p4 * m4.x; a1 += p4 * m4.y; a2 += p4 * m4.z; a3 += p4 * m4.w;
        }
        float sgn = (k3 & 2) ? -1.0f : 1.0f;                 // s_k: +,+,-,- (period 4)
        float* xd = &sm[S_X + lp * 1248 + k3 * 32 + jq * 4];
        xd[0] = sgn * a0; xd[1] = sgn * a1; xd[2] = sgn * a2; xd[3] = sgn * a3;
    }
    __syncthreads();

    if (!valid) return;                                       // no syncs after this

    // -------- Phase D: per-warp seeds (reads PT smem + g_tab global) --------
    const int k1 = pair / 39, k2 = pair - (pair / 39) * 39;
    const float* t1r = g_tab + k1 * 1024;
    const float* t2r = g_tab + k2 * 1024;
    const float* cr  = g_tab + 1024;                          // k=1 row: cos(a)

    ull w0[16], w1[16], p2[16], m2[16];
#pragma unroll
    for (int jp = 0; jp < 16; jp++) {
        int t0 = (2 * jp) * 32 + lane, t1 = t0 + 32;
        float pa = sm[S_PT + (2 * jp) * 33 + lane];
        float pb = sm[S_PT + (2 * jp + 1) * 33 + lane];
        float a0 = pa * t1r[t0] * t2r[t0];                    // A[i, 2jp]
        float a1 = pb * t1r[t1] * t2r[t1];                    // A[i, 2jp+1]
        float c0 = cr[t0], c1 = cr[t1];
        w0[jp] = f2_pack2(a0, a1);                            // w_0 = A
        w1[jp] = f2_pack2(a0 * c0, a1 * c1);                  // w_1 = A*c
        p2[jp] = f2_pack2(2.0f * c0, 2.0f * c1);              // +2c
        m2[jp] = f2_pack2(-2.0f * c0, -2.0f * c1);            // -2c
    }

    // -------- Phase E: march k3, accumulate, store --------
    const float* xrow = sm + S_X + wid * 1248;
    float* outp = out + pair * (NP * 32) + lane;

#define ACC_STORE(K3, W) do {                                             \
    const ulonglong2* xq = (const ulonglong2*)(xrow + (K3) * 32);         \
    ull a0 = 0, a1 = 0, a2 = 0, a3 = 0;                                   \
    _Pragma("unroll")                                                     \
    for (int q = 0; q < 8; q += 2) {                                      \
        ulonglong2 xv0 = xq[q], xv1 = xq[q + 1];                          \
        a0 = f2_fma(W[2*q + 0], xv0.x, a0);                               \
        a1 = f2_fma(W[2*q + 1], xv0.y, a1);                               \
        a2 = f2_fma(W[2*q + 2], xv1.x, a2);                               \
        a3 = f2_fma(W[2*q + 3], xv1.y, a3);                               \
    }                                                                     \
    float2 fr = f2_unpack(f2_add(f2_add(a0, a1), f2_add(a2, a3)));        \
    outp[(K3) * 32] = fr.x + fr.y;                                        \
} while (0)

    ACC_STORE(0, w0);
    ACC_STORE(1, w1);

#pragma unroll 1
    for (int k3 = 2; k3 < 38; k3 += 2) {
        // even step: w_k = (-2c)*w_{k-1} + w_{k-2}
#pragma unroll
        for (int jp = 0; jp < 16; jp++) w0[jp] = f2_fma(m2[jp], w1[jp], w0[jp]);
        ACC_STORE(k3, w0);
        // odd step: w_{k+1} = (+2c)*w_k + w_{k-1}
#pragma unroll
        for (int jp = 0; jp < 16; jp++) w1[jp] = f2_fma(p2[jp], w0[jp], w1[jp]);
        ACC_STORE(k3 + 1, w1);
    }
    // k3 = 38 (even)
#pragma unroll
    for (int jp = 0; jp < 16; jp++) w0[jp] = f2_fma(m2[jp], w1[jp], w0[jp]);
    ACC_STORE(38, w0);
#undef ACC_STORE
}

// ---------------------------------------------------------------------------
extern "C" void kernel_launch(void* const* d_in, const int* in_sizes, int n_in,
                              void* d_out, int out_size) {
    const float* vol = (const float*)d_in[0];
    const float* M   = (const float*)d_in[1];
    const float* P   = (const float*)d_in[2];
    float* out = (float*)d_out;

    static int attr_set = 0;
    if (!attr_set) {
        cudaFuncSetAttribute(k_fused, cudaFuncAttributeMaxDynamicSharedMemorySize,
                             SMEM_FLOATS * 4);
        attr_set = 1;
    }
    const int nblk = (NPAIR + WPB - 1) / WPB;   // 127
    k_pre  <<<4, 256>>>();
    k_fused<<<nblk, TPB, SMEM_FLOATS * 4>>>(vol, M, P, out);
}

// round 10
// speedup vs baseline: 2.1123x; 1.0023x over previous
#include <cuda_runtime.h>

// Problem: volume [40,40,40,32] f32, M [32,32], P [32,32] -> Nk [59319,32]
//   b = (k1*39 + k2)*39 + k3
//   Nk[b,i] = sum_j x[b,j] * P[i,j] * cos(k1*a_ij) * cos(k2*a_ij) * cos(k3*a_ij)
//   a_ij = 2pi/(i*32+j+2),  x = (2x2x2 mean pool) @ M^T
//
// k_fused: one warp per (k1,k2) pair. Lane = i. j packed into 16 f32x2 regs.
// k3 marched by in-register Chebyshev recurrence (NO cos loads in hot loop):
//   u_k = 2c*u_{k-1} - u_{k-2};  w_k = s_k*u_k, s = (+,+,-,-) period 4
//   even k: w = fma(-2c, w1, w0); odd k: w = fma(+2c, w0, w1)  (pure FMA)
// Sign s_k folded into staged x rows; s^2 = 1 cancels in the product.
// R10: WPB 12->11 (grid 139, reg ceiling 186), x-row LDS hoisted ahead of the
// recurrence FMAs so shared-memory latency is covered by independent issue.
#define NP    39
#define NPAIR (39*39)     // 1521
#define WPB   11          // pairs (warps) per block
#define TPB   (WPB*32)    // 352
#define PI2F  6.2831853071795864769f

typedef unsigned long long ull;

__device__ float g_tab[39 * 1024];   // tab[k][j*32+i] = cos(k*2pi/(i*32+j+2))

// ---- f32x2 packed math (sm_103a) ------------------------------------------
__device__ __forceinline__ ull f2_fma(ull a, ull b, ull c) {
    ull d; asm("fma.rn.f32x2 %0, %1, %2, %3;" : "=l"(d) : "l"(a), "l"(b), "l"(c)); return d;
}
__device__ __forceinline__ ull f2_add(ull a, ull b) {
    ull d; asm("add.rn.f32x2 %0, %1, %2;" : "=l"(d) : "l"(a), "l"(b)); return d;
}
__device__ __forceinline__ ull f2_pack2(float lo, float hi) {
    ull d; asm("mov.b64 %0, {%1, %2};" : "=l"(d) : "f"(lo), "f"(hi)); return d;
}
__device__ __forceinline__ float2 f2_unpack(ull v) {
    float2 r; asm("mov.b64 {%0, %1}, %2;" : "=f"(r.x), "=f"(r.y) : "l"(v)); return r;
}

// ---------------------------------------------------------------------------
// Kernel 0: cos table via Chebyshev recurrence. grid 4 x 256.
// ---------------------------------------------------------------------------
__global__ void k_pre() {
    int t = blockIdx.x * 256 + threadIdx.x;   // t = j*32 + i
    int i = t & 31, j = t >> 5;
    float a  = PI2F / (float)(i * 32 + j + 2);
    float c1 = cosf(a);
    float twoc = 2.0f * c1;
    float cm2 = 1.0f, cm1 = c1;
    g_tab[t]        = 1.0f;
    g_tab[1024 + t] = c1;
#pragma unroll
    for (int k = 2; k < 39; k++) {
        float ck = twoc * cm1 - cm2;
        g_tab[k * 1024 + t] = ck;
        cm2 = cm1; cm1 = ck;
    }
}

// ---------------------------------------------------------------------------
// Fused kernel. grid 139 x 352 threads; 129.3 KB dynamic smem.
// ---------------------------------------------------------------------------
// smem float offsets:
#define S_MS    0        // 1056   M padded  [j*33 + l]
#define S_PT    1056     // 1056   P^T padded [j*33 + i]
#define S_MT    2112     // 1024   MT[l*32 + j] = M[j][l]
#define S_POOL  3136     // 11*1404 = 15444  pooled[lp][k3*36 + ch]
#define S_X     18580    // 11*1248 = 13728  x'[lp][k3*32 + j] (sign folded)
#define SMEM_FLOATS 32308

__global__ void __launch_bounds__(TPB) k_fused(
    const float* __restrict__ vol, const float* __restrict__ Mw,
    const float* __restrict__ P, float* __restrict__ out)
{
    extern __shared__ float sm[];
    const int tid  = threadIdx.x;
    const int wid  = tid >> 5;
    const int lane = tid & 31;
    const int pair = blockIdx.x * WPB + wid;
    const bool valid = (pair < NPAIR);

    // -------- Phase A: stage padded M and transposed-padded P --------
    for (int g = tid; g < 1024; g += TPB) {
        sm[S_MS + (g >> 5) * 33 + (g & 31)] = Mw[g];          // MS[j][l]
        sm[S_PT + (g & 31) * 33 + (g >> 5)] = P[g];           // PT[j][i] = P[i][j]
    }
    __syncthreads();

    // -------- Phase B: MT transpose + pooling (11 pairs) --------
    for (int t = tid; t < 1024; t += TPB)
        sm[S_MT + t] = sm[S_MS + (t & 31) * 33 + (t >> 5)];   // MT[l][j] = M[j][l]

    for (int job = tid; job < WPB * 312; job += TPB) {
        int lp  = job / 312;
        int rem = job - lp * 312;
        int k3  = rem >> 3;
        int cq  = rem & 7;
        int gp  = blockIdx.x * WPB + lp;
        if (gp >= NPAIR) continue;
        int kk1 = gp / 39, kk2 = gp - kk1 * 39;
        const float* base = vol + (((kk1 * 40) + kk2) * 40 + k3) * 32 + cq * 4;
        float4 s = make_float4(0.f, 0.f, 0.f, 0.f);
#pragma unroll
        for (int dd = 0; dd < 2; dd++)
#pragma unroll
            for (int hh = 0; hh < 2; hh++)
#pragma unroll
                for (int ww = 0; ww < 2; ww++) {
                    float4 v = *(const float4*)(base + dd * 51200 + hh * 1280 + ww * 32);
                    s.x += v.x; s.y += v.y; s.z += v.z; s.w += v.w;
                }
        s.x *= 0.125f; s.y *= 0.125f; s.z *= 0.125f; s.w *= 0.125f;
        *(float4*)&sm[S_POOL + lp * 1404 + k3 * 36 + cq * 4] = s;
    }
    __syncthreads();

    // -------- Phase C: matvec x'[lp][k3][j] = s_k3 * (pooled @ M^T) --------
    for (int job = tid; job < WPB * 312; job += TPB) {
        int lp  = job / 312;
        int rem = job - lp * 312;
        int k3  = rem >> 3;
        int jq  = rem & 7;
        int gp  = blockIdx.x * WPB + lp;
        if (gp >= NPAIR) continue;
        float a0 = 0.f, a1 = 0.f, a2 = 0.f, a3 = 0.f;
#pragma unroll
        for (int l = 0; l < 32; l++) {
            float p4 = sm[S_POOL + lp * 1404 + k3 * 36 + l];
            float4 m4 = *(const float4*)&sm[S_MT + l * 32 + jq * 4];
            a0 += p4 * m4.x; a1 += p4 * m4.y; a2 += p4 * m4.z; a3 += p4 * m4.w;
        }
        float sgn = (k3 & 2) ? -1.0f : 1.0f;                 // s_k: +,+,-,- (period 4)
        float* xd = &sm[S_X + lp * 1248 + k3 * 32 + jq * 4];
        xd[0] = sgn * a0; xd[1] = sgn * a1; xd[2] = sgn * a2; xd[3] = sgn * a3;
    }
    __syncthreads();

    if (!valid) return;                                       // no syncs after this

    // -------- Phase D: per-warp seeds (reads PT smem + g_tab global) --------
    const int k1 = pair / 39, k2 = pair - (pair / 39) * 39;
    const float* t1r = g_tab + k1 * 1024;
    const float* t2r = g_tab + k2 * 1024;
    const float* cr  = g_tab + 1024;                          // k=1 row: cos(a)

    ull w0[16], w1[16], p2[16], m2[16];
#pragma unroll
    for (int jp = 0; jp < 16; jp++) {
        int t0 = (2 * jp) * 32 + lane, t1 = t0 + 32;
        float pa = sm[S_PT + (2 * jp) * 33 + lane];
        float pb = sm[S_PT + (2 * jp + 1) * 33 + lane];
        float a0 = pa * t1r[t0] * t2r[t0];                    // A[i, 2jp]
        float a1 = pb * t1r[t1] * t2r[t1];                    // A[i, 2jp+1]
        float c0 = cr[t0], c1 = cr[t1];
        w0[jp] = f2_pack2(a0, a1);                            // w_0 = A
        w1[jp] = f2_pack2(a0 * c0, a1 * c1);                  // w_1 = A*c
        p2[jp] = f2_pack2(2.0f * c0, 2.0f * c1);              // +2c
        m2[jp] = f2_pack2(-2.0f * c0, -2.0f * c1);            // -2c
    }

    // -------- Phase E: march k3; x-row loads hoisted ahead of recurrence ----
    const ulonglong2* xq = (const ulonglong2*)(sm + S_X + wid * 1248);
    float* outp = out + pair * (NP * 32) + lane;
    ulonglong2 xb[8];

#define XLOAD(K3) do { _Pragma("unroll")                                  \
    for (int q = 0; q < 8; q++) xb[q] = xq[(K3) * 8 + q]; } while (0)

#define DOT_TAIL(W, K3) do {                                              \
    ull a0 = 0, a1 = 0, a2 = 0, a3 = 0;                                   \
    _Pragma("unroll")                                                     \
    for (int q = 0; q < 8; q += 2) {                                      \
        a0 = f2_fma(W[2*q + 0], xb[q].x,     a0);                         \
        a1 = f2_fma(W[2*q + 1], xb[q].y,     a1);                         \
        a2 = f2_fma(W[2*q + 2], xb[q + 1].x, a2);                         \
        a3 = f2_fma(W[2*q + 3], xb[q + 1].y, a3);                         \
    }                                                                     \
    float2 fr = f2_unpack(f2_add(f2_add(a0, a1), f2_add(a2, a3)));        \
    outp[(K3) * 32] = fr.x + fr.y;                                        \
} while (0)

    XLOAD(0); DOT_TAIL(w0, 0);
    XLOAD(1); DOT_TAIL(w1, 1);

#pragma unroll 1
    for (int k3 = 2; k3 < 38; k3 += 2) {
        XLOAD(k3);                                            // LDS first...
#pragma unroll
        for (int jp = 0; jp < 16; jp++)                       // ...covered by FMAs
            w0[jp] = f2_fma(m2[jp], w1[jp], w0[jp]);          // even: w = -2c*w1 + w0
        DOT_TAIL(w0, k3);
        XLOAD(k3 + 1);
#pragma unroll
        for (int jp = 0; jp < 16; jp++)
            w1[jp] = f2_fma(p2[jp], w0[jp], w1[jp]);          // odd: w = +2c*w0 + w1
        DOT_TAIL(w1, k3 + 1);
    }
    // k3 = 38 (even)
    XLOAD(38);
#pragma unroll
    for (int jp = 0; jp < 16; jp++)
        w0[jp] = f2_fma(m2[jp], w1[jp], w0[jp]);
    DOT_TAIL(w0, 38);
#undef XLOAD
#undef DOT_TAIL
}

// ---------------------------------------------------------------------------
extern "C" void kernel_launch(void* const* d_in, const int* in_sizes, int n_in,
                              void* d_out, int out_size) {
    const float* vol = (const float*)d_in[0];
    const float* M   = (const float*)d_in[1];
    const float* P   = (const float*)d_in[2];
    float* out = (float*)d_out;

    static int attr_set = 0;
    if (!attr_set) {
        cudaFuncSetAttribute(k_fused, cudaFuncAttributeMaxDynamicSharedMemorySize,
                             SMEM_FLOATS * 4);
        attr_set = 1;
    }
    const int nblk = (NPAIR + WPB - 1) / WPB;   // 139
    k_pre  <<<4, 256>>>();
    k_fused<<<nblk, TPB, SMEM_FLOATS * 4>>>(vol, M, P, out);
}